// round 13
// baseline (speedup 1.0000x reference)
#include <cuda_runtime.h>
#include <cuda_fp16.h>
#include <cstdint>

// Problem constants
#define NN   100000   // nodes
#define RR   4        // relations
#define EE   500000   // edges per relation
#define FIN  256
#define FHID 128
#define FOUT 64

#define NSC  (RR * NN)                   // scan length (400000)
#define NB   ((NSC + 1023) / 1024)       // scan blocks (391)
#define FULL 0xffffffffu

// ---------------------------------------------------------------------------
// Scratch (static device globals). ONLY referenced from device code — passing
// these symbols as kernel args from host code yields the host-shadow address,
// which GB300 ATS silently dereferences into HOST memory (R5/R6 bug).
// ---------------------------------------------------------------------------
__device__ __align__(256) float  g_dinv_out[RR * NN];          // rsqrt(out-degree)
__device__ __align__(256) float  g_dinv_in [RR * NN];          // rsqrt(in-degree)
__device__ __align__(256) __half g_h16[(size_t)NN * FHID];     // per-relation transform (fp16)
__device__ __align__(256) float  g_acc1[(size_t)NN * FHID];    // layer-1 aggregate (fp32)
__device__ __align__(256) float  g_sb1[FHID];                  // sum_r b1[r]
// CSR build
__device__ __align__(256) int    g_cnt   [NSC];                // dst histogram per relation
__device__ __align__(256) int    g_rowptr[NSC];                // exclusive scan of g_cnt
__device__ __align__(256) int    g_wptr  [NSC];                // write cursors (placement)
__device__ __align__(256) int    g_bsum  [512];                // scan block sums
__device__ __align__(256) int    g_srt   [RR * EE];            // src ids, dst-sorted per relation

// ---------------------------------------------------------------------------
// Zero scratch; initialize out[m][n] = sum_r b2[r][n]
// ---------------------------------------------------------------------------
__global__ void zero_all(float4* __restrict__ out4, const float* __restrict__ b2) {
    int i = blockIdx.x * blockDim.x + threadIdx.x;
    int stride = gridDim.x * blockDim.x;
    float4 z = make_float4(0.f, 0.f, 0.f, 0.f);
    float4* dout4 = (float4*)g_dinv_out;
    int4*   cnt4  = (int4*)g_cnt;
    float4* acc4  = (float4*)g_acc1;
    int4 zi = make_int4(0, 0, 0, 0);
    for (int j = i; j < NSC / 4; j += stride) { dout4[j] = z; cnt4[j] = zi; }
    for (int j = i; j < (NN * FHID) / 4; j += stride) acc4[j] = z;
    for (int j = i; j < (NN * FOUT) / 4; j += stride) {
        int c = (j % (FOUT / 4)) * 4;
        float4 v;
        v.x = b2[c+0] + b2[FOUT+c+0] + b2[2*FOUT+c+0] + b2[3*FOUT+c+0];
        v.y = b2[c+1] + b2[FOUT+c+1] + b2[2*FOUT+c+1] + b2[3*FOUT+c+1];
        v.z = b2[c+2] + b2[FOUT+c+2] + b2[2*FOUT+c+2] + b2[3*FOUT+c+2];
        v.w = b2[c+3] + b2[FOUT+c+3] + b2[2*FOUT+c+3] + b2[3*FOUT+c+3];
        out4[j] = v;
    }
}

// ---------------------------------------------------------------------------
// Degrees: int histogram on dst (drives dinv_in + CSR), float accum on src
// ---------------------------------------------------------------------------
__global__ void degree_kernel(const int* __restrict__ src, const int* __restrict__ dst) {
    int t = blockIdx.x * blockDim.x + threadIdx.x;
    if (t >= RR * EE) return;
    int r = t / EE;
    atomicAdd(&g_cnt[r * NN + dst[t]], 1);
    atomicAdd(&g_dinv_out[r * NN + src[t]], 1.0f);
}

// rsqrt of degrees + sb1 = sum_r b1[r]
__global__ void rsqrt_kernel(const float* __restrict__ b1) {
    int t = blockIdx.x * blockDim.x + threadIdx.x;
    if (t < FHID) {
        float s = 0.f;
        #pragma unroll
        for (int r = 0; r < RR; r++) s += b1[r * FHID + t];
        g_sb1[t] = s;
    }
    if (t >= NSC) return;
    g_dinv_out[t] = rsqrtf(fmaxf(g_dinv_out[t], 1.0f));
    g_dinv_in [t] = rsqrtf(fmaxf((float)g_cnt[t], 1.0f));
}

// ---------------------------------------------------------------------------
// Two-level exclusive scan of g_cnt -> g_rowptr (+ g_wptr copy)
// ---------------------------------------------------------------------------
__global__ void scan1() {
    __shared__ int sh[256];
    int tid = threadIdx.x;
    int i0 = blockIdx.x * 1024 + tid * 4;
    int a0 = (i0 + 0 < NSC) ? g_cnt[i0 + 0] : 0;
    int a1 = (i0 + 1 < NSC) ? g_cnt[i0 + 1] : 0;
    int a2 = (i0 + 2 < NSC) ? g_cnt[i0 + 2] : 0;
    int a3 = (i0 + 3 < NSC) ? g_cnt[i0 + 3] : 0;
    int s0 = a0, s1 = s0 + a1, s2 = s1 + a2, s3 = s2 + a3;
    sh[tid] = s3;
    __syncthreads();
    for (int d = 1; d < 256; d <<= 1) {
        int v = (tid >= d) ? sh[tid - d] : 0;
        __syncthreads();
        sh[tid] += v;
        __syncthreads();
    }
    int ex = sh[tid] - s3;
    if (i0 + 0 < NSC) g_rowptr[i0 + 0] = ex;
    if (i0 + 1 < NSC) g_rowptr[i0 + 1] = ex + s0;
    if (i0 + 2 < NSC) g_rowptr[i0 + 2] = ex + s1;
    if (i0 + 3 < NSC) g_rowptr[i0 + 3] = ex + s2;
    if (tid == 255) g_bsum[blockIdx.x] = sh[255];
}

__global__ void scan2() {
    __shared__ int sh[512];
    int tid = threadIdx.x;
    int v = (tid < NB) ? g_bsum[tid] : 0;
    sh[tid] = v;
    __syncthreads();
    for (int d = 1; d < 512; d <<= 1) {
        int u = (tid >= d) ? sh[tid - d] : 0;
        __syncthreads();
        sh[tid] += u;
        __syncthreads();
    }
    if (tid < NB) g_bsum[tid] = sh[tid] - v;
}

__global__ void scan3() {
    int add = g_bsum[blockIdx.x];
    int i0 = blockIdx.x * 1024 + threadIdx.x * 4;
    #pragma unroll
    for (int j = 0; j < 4; j++) {
        int i = i0 + j;
        if (i < NSC) {
            int v = g_rowptr[i] + add;
            g_rowptr[i] = v;
            g_wptr[i] = v;
        }
    }
}

__global__ void place_kernel(const int* __restrict__ src, const int* __restrict__ dst) {
    int t = blockIdx.x * blockDim.x + threadIdx.x;
    if (t >= RR * EE) return;
    int r = t / EE;
    int pos = atomicAdd(&g_wptr[r * NN + dst[t]], 1);
    g_srt[pos] = src[t];
}

// ---------------------------------------------------------------------------
// TF32 / cp.async helpers
// ---------------------------------------------------------------------------
__device__ __forceinline__ uint32_t f2tf32(float x) {
    uint32_t u;
    asm("cvt.rna.tf32.f32 %0, %1;" : "=r"(u) : "f"(x));
    return u;
}

__device__ __forceinline__ void mma_tf32(float* c, const uint32_t* a,
                                         uint32_t b0, uint32_t b1) {
    asm volatile(
        "mma.sync.aligned.m16n8k8.row.col.f32.tf32.tf32.f32 "
        "{%0,%1,%2,%3}, {%4,%5,%6,%7}, {%8,%9}, {%0,%1,%2,%3};"
        : "+f"(c[0]), "+f"(c[1]), "+f"(c[2]), "+f"(c[3])
        : "r"(a[0]), "r"(a[1]), "r"(a[2]), "r"(a[3]), "r"(b0), "r"(b1));
}

__device__ __forceinline__ void cp16(uint32_t smem, const void* g, int srcbytes) {
    asm volatile("cp.async.cg.shared.global [%0], [%1], 16, %2;"
                 :: "r"(smem), "l"(g), "r"(srcbytes));
}
__device__ __forceinline__ void cp_commit() {
    asm volatile("cp.async.commit_group;");
}
template <int N>
__device__ __forceinline__ void cp_wait() {
    asm volatile("cp.async.wait_group %0;" :: "n"(N));
}

// ---------------------------------------------------------------------------
// Layer-1 GEMM: cp.async double-buffered TF32, writes g_h16 (fp16):
//   g_h16[m][n] = half( dinv_out[r][m] * sum_k x[m][k] * W1[r][k][n] )
// Raw fp32 goes straight to smem (LDGSTS); the tf32 MMA truncates the
// mantissa in hardware (CUTLASS-style) — no cvt, no register staging.
// BM=128, BN=128, BK=16, 2 stages, 256 threads = 8 warps (4m x 2n).
// Smem/stage 19KB -> 38KB static total; high occupancy.
// ---------------------------------------------------------------------------
__global__ void __launch_bounds__(256)
gemm1_tc(const float* __restrict__ A,     // x [M][FIN]
         const float* __restrict__ W,     // W1 [R][FIN][FHID]
         int M, int r)
{
    constexpr int BM = 128, BN = 128, BK = 16, KT = FIN / BK;  // 16 k-tiles
    constexpr int ASTR = BK + 4;          // 20: frag bank = (20g)%32 distinct
    constexpr int BSTR = BN + 8;          // 136: frag bank = (8tig+g) distinct
    constexpr int WN = BN / 2, NT = WN / 8;

    __shared__ uint32_t As[2][BM * ASTR];
    __shared__ uint32_t Bs[2][BK * BSTR];

    const float* B = W + (size_t)r * FIN * BN;
    const int tid  = threadIdx.x;
    const int wid  = tid >> 5;
    const int lane = tid & 31;
    const int g    = lane >> 2;
    const int tig  = lane & 3;
    const int warp_m = wid & 3;
    const int warp_n = wid >> 2;
    const int rowBase = blockIdx.x * BM;

    // A: 128x16 floats = 512 chunks of 16B; 2 per thread
    const int arow = tid >> 2;            // chunk row for i=0 is tid/4 over 64 rows? no:
    // f = i*256 + tid; arow = f/4, ac4 = f%4  (BK/4 = 4 chunks/row)
    // B: 16x128 floats = 512 chunks; brow = f/32, bc4 = f%32

    auto load_stage = [&](int s, int k0) {
        #pragma unroll
        for (int i = 0; i < 2; i++) {
            int f = i * 256 + tid;
            int ar = f >> 2;
            int ac = f & 3;
            int grow = rowBase + ar;
            const float* gp = A + (size_t)(grow < M ? grow : 0) * FIN + k0 + ac * 4;
            uint32_t sm = (uint32_t)__cvta_generic_to_shared(&As[s][ar * ASTR + ac * 4]);
            cp16(sm, gp, grow < M ? 16 : 0);
        }
        #pragma unroll
        for (int i = 0; i < 2; i++) {
            int f = i * 256 + tid;
            int br = f >> 5;
            int bc = f & 31;
            const float* gp = B + (size_t)(k0 + br) * BN + bc * 4;
            uint32_t sm = (uint32_t)__cvta_generic_to_shared(&Bs[s][br * BSTR + bc * 4]);
            cp16(sm, gp, 16);
        }
    };

    float acc[2][NT][4];
    #pragma unroll
    for (int mt = 0; mt < 2; mt++)
        #pragma unroll
        for (int nt = 0; nt < NT; nt++)
            #pragma unroll
            for (int j = 0; j < 4; j++) acc[mt][nt][j] = 0.f;

    auto compute = [&](int s) {
        #pragma unroll
        for (int ks = 0; ks < BK / 8; ks++) {
            int k8 = ks * 8;
            uint32_t a[2][4];
            #pragma unroll
            for (int mt = 0; mt < 2; mt++) {
                int rb = warp_m * 32 + mt * 16;
                a[mt][0] = As[s][(rb + g)     * ASTR + k8 + tig];
                a[mt][1] = As[s][(rb + g + 8) * ASTR + k8 + tig];
                a[mt][2] = As[s][(rb + g)     * ASTR + k8 + tig + 4];
                a[mt][3] = As[s][(rb + g + 8) * ASTR + k8 + tig + 4];
            }
            #pragma unroll
            for (int nt = 0; nt < NT; nt++) {
                int cb = warp_n * WN + nt * 8;
                uint32_t b0 = Bs[s][(k8 + tig)     * BSTR + cb + g];
                uint32_t b1 = Bs[s][(k8 + tig + 4) * BSTR + cb + g];
                #pragma unroll
                for (int mt = 0; mt < 2; mt++)
                    mma_tf32(acc[mt][nt], a[mt], b0, b1);
            }
        }
    };

    load_stage(0, 0);
    cp_commit();
    for (int it = 0; it < KT; it++) {
        if (it + 1 < KT) {
            load_stage((it + 1) & 1, (it + 1) * BK);
            cp_commit();
            cp_wait<1>();
        } else {
            cp_wait<0>();
        }
        __syncthreads();
        compute(it & 1);
        __syncthreads();
    }

    // epilogue: scale by dinv_out, store fp16
    #pragma unroll
    for (int mt = 0; mt < 2; mt++) {
        int row0 = rowBase + warp_m * 32 + mt * 16 + g;
        int row1 = row0 + 8;
        float s0 = (row0 < M) ? g_dinv_out[(size_t)r * NN + row0] : 0.f;
        float s1 = (row1 < M) ? g_dinv_out[(size_t)r * NN + row1] : 0.f;
        #pragma unroll
        for (int nt = 0; nt < NT; nt++) {
            int col = warp_n * WN + nt * 8 + 2 * tig;
            if (row0 < M)
                *(__half2*)&g_h16[(size_t)row0 * BN + col] =
                    __floats2half2_rn(acc[mt][nt][0] * s0, acc[mt][nt][1] * s0);
            if (row1 < M)
                *(__half2*)&g_h16[(size_t)row1 * BN + col] =
                    __floats2half2_rn(acc[mt][nt][2] * s1, acc[mt][nt][3] * s1);
        }
    }
}

// ---------------------------------------------------------------------------
// Layer-2 GEMM: register-staged TF32 (R11-validated path) — needs the fused
// relu(acc1 + sb1) transform on the A-load, so no raw cp.async here.
//   g_h16[m][n] = half( dinv_out[r][m] * sum_k relu(acc1[m][k]+sb1[k]) * W2[r][k][n] )
// ---------------------------------------------------------------------------
__global__ void __launch_bounds__(256, 2)
gemm2_tc(const float* __restrict__ W, int M, int r)
{
    constexpr int BN = FOUT, BM = 128, BK = 32, K = FHID;
    constexpr int APT  = BM * BK / 4 / 256;
    constexpr int BPT  = BK * BN / 4 / 256;
    constexpr int ASTR = BK + 4;
    constexpr int BSTR = BN + 8;
    constexpr int WN   = BN / 2;
    constexpr int NT   = WN / 8;

    __shared__ uint32_t As[BM * ASTR];
    __shared__ uint32_t Bs[BK * BSTR];

    const float* A = g_acc1;
    const float* B = W + (size_t)r * K * BN;

    const int tid  = threadIdx.x;
    const int wid  = tid >> 5;
    const int lane = tid & 31;
    const int g    = lane >> 2;
    const int tig  = lane & 3;
    const int warp_m = wid & 3;
    const int warp_n = wid >> 2;
    const int rowBase = blockIdx.x * BM;

    float acc[2][NT][4];
    #pragma unroll
    for (int mt = 0; mt < 2; mt++)
        #pragma unroll
        for (int nt = 0; nt < NT; nt++)
            #pragma unroll
            for (int j = 0; j < 4; j++) acc[mt][nt][j] = 0.f;

    float4 aReg[APT], bReg[BPT];

    auto load_regs = [&](int k0) {
        #pragma unroll
        for (int i = 0; i < APT; i++) {
            int f = i * 256 + tid;
            int ar = f >> 3;
            int ac = f & 7;
            int grow = rowBase + ar;
            float4 v = make_float4(0.f, 0.f, 0.f, 0.f);
            if (grow < M)
                v = *(const float4*)(A + (size_t)grow * K + k0 + ac * 4);
            aReg[i] = v;
        }
        #pragma unroll
        for (int i = 0; i < BPT; i++) {
            int f = i * 256 + tid;
            int br = f / (BN / 4);
            int bc = f % (BN / 4);
            bReg[i] = *(const float4*)(B + (size_t)(k0 + br) * BN + bc * 4);
        }
    };

    auto store_smem = [&](int kload) {
        #pragma unroll
        for (int i = 0; i < APT; i++) {
            int f = i * 256 + tid;
            int ar = f >> 3;
            int ac = f & 7;
            float4 v = aReg[i];
            const float* bb = g_sb1 + kload + ac * 4;
            v.x = fmaxf(v.x + bb[0], 0.f);
            v.y = fmaxf(v.y + bb[1], 0.f);
            v.z = fmaxf(v.z + bb[2], 0.f);
            v.w = fmaxf(v.w + bb[3], 0.f);
            uint4 u = make_uint4(f2tf32(v.x), f2tf32(v.y), f2tf32(v.z), f2tf32(v.w));
            *(uint4*)&As[ar * ASTR + ac * 4] = u;
        }
        #pragma unroll
        for (int i = 0; i < BPT; i++) {
            int f = i * 256 + tid;
            int br = f / (BN / 4);
            int bc = f % (BN / 4);
            float4 v = bReg[i];
            uint4 u = make_uint4(f2tf32(v.x), f2tf32(v.y), f2tf32(v.z), f2tf32(v.w));
            *(uint4*)&Bs[br * BSTR + bc * 4] = u;
        }
    };

    auto compute = [&]() {
        #pragma unroll
        for (int ks = 0; ks < 4; ks++) {
            int k8 = ks * 8;
            uint32_t a[2][4];
            #pragma unroll
            for (int mt = 0; mt < 2; mt++) {
                int rb = warp_m * 32 + mt * 16;
                a[mt][0] = As[(rb + g)     * ASTR + k8 + tig];
                a[mt][1] = As[(rb + g + 8) * ASTR + k8 + tig];
                a[mt][2] = As[(rb + g)     * ASTR + k8 + tig + 4];
                a[mt][3] = As[(rb + g + 8) * ASTR + k8 + tig + 4];
            }
            #pragma unroll
            for (int nt = 0; nt < NT; nt++) {
                int cb = warp_n * WN + nt * 8;
                uint32_t b0 = Bs[(k8 + tig)     * BSTR + cb + g];
                uint32_t b1 = Bs[(k8 + tig + 4) * BSTR + cb + g];
                #pragma unroll
                for (int mt = 0; mt < 2; mt++)
                    mma_tf32(acc[mt][nt], a[mt], b0, b1);
            }
        }
    };

    load_regs(0);
    store_smem(0);
    __syncthreads();
    for (int k0 = BK; k0 < K; k0 += BK) {
        load_regs(k0);
        compute();
        __syncthreads();
        store_smem(k0);
        __syncthreads();
    }
    compute();

    #pragma unroll
    for (int mt = 0; mt < 2; mt++) {
        int row0 = rowBase + warp_m * 32 + mt * 16 + g;
        int row1 = row0 + 8;
        float s0 = (row0 < M) ? g_dinv_out[(size_t)r * NN + row0] : 0.f;
        float s1 = (row1 < M) ? g_dinv_out[(size_t)r * NN + row1] : 0.f;
        #pragma unroll
        for (int nt = 0; nt < NT; nt++) {
            int col = warp_n * WN + nt * 8 + 2 * tig;
            if (row0 < M)
                *(__half2*)&g_h16[(size_t)row0 * BN + col] =
                    __floats2half2_rn(acc[mt][nt][0] * s0, acc[mt][nt][1] * s0);
            if (row1 < M)
                *(__half2*)&g_h16[(size_t)row1 * BN + col] =
                    __floats2half2_rn(acc[mt][nt][2] * s1, acc[mt][nt][3] * s1);
        }
    }
}

// ---------------------------------------------------------------------------
// CSR gather-aggregation, no atomics. Warp-coalesced src-id prefetch:
// one coalesced g_srt load per 32 edges, ids broadcast via shuffle (26 cyc)
// instead of a dependent per-edge L2 load (~250 cyc).
// ---------------------------------------------------------------------------
__device__ __forceinline__ void h4_acc(float4& a, uint2 raw) {
    float2 f01 = __half22float2(*(__half2*)&raw.x);
    float2 f23 = __half22float2(*(__half2*)&raw.y);
    a.x += f01.x; a.y += f01.y; a.z += f23.x; a.w += f23.y;
}

// Layer 1: g_acc1[d] += dinv_in[r][d] * sum_{e in CSR_r[d]} h16[src_e]  (128 feats)
__global__ void __launch_bounds__(256)
gather128(int r) {
    int w = (blockIdx.x * blockDim.x + threadIdx.x) >> 5;
    if (w >= NN) return;
    int lane = threadIdx.x & 31;
    int idx = r * NN + w;
    int beg = g_rowptr[idx];
    int end = (idx == NSC - 1) ? RR * EE : g_rowptr[idx + 1];
    if (beg == end) return;
    const uint2* h = (const uint2*)g_h16;
    float4 a0 = make_float4(0.f, 0.f, 0.f, 0.f);
    float4 a1 = make_float4(0.f, 0.f, 0.f, 0.f);
    int n = end - beg;
    while (n > 0) {
        int take = n < 32 ? n : 32;
        int sid = (lane < take) ? g_srt[beg + lane] : 0;   // coalesced batch load
        int j = 0;
        for (; j + 2 <= take; j += 2) {
            int s0 = __shfl_sync(FULL, sid, j);
            int s1 = __shfl_sync(FULL, sid, j + 1);
            uint2 r0 = h[(size_t)s0 * (FHID / 4) + lane];
            uint2 r1 = h[(size_t)s1 * (FHID / 4) + lane];
            h4_acc(a0, r0);
            h4_acc(a1, r1);
        }
        if (j < take) {
            int s0 = __shfl_sync(FULL, sid, j);
            uint2 r0 = h[(size_t)s0 * (FHID / 4) + lane];
            h4_acc(a0, r0);
        }
        beg += take;
        n -= take;
    }
    float sc = g_dinv_in[idx];
    float4* acc4 = (float4*)g_acc1;
    size_t o = (size_t)w * (FHID / 4) + lane;
    float4 cur = acc4[o];
    cur.x += sc * (a0.x + a1.x);
    cur.y += sc * (a0.y + a1.y);
    cur.z += sc * (a0.z + a1.z);
    cur.w += sc * (a0.w + a1.w);
    acc4[o] = cur;
}

// Layer 2: out[d] += dinv_in[r][d] * sum h16[src]  (64 feats).
// Two edges per warp: lanes 0-15 take even edges, 16-31 odd (uint2 each),
// cross-reduced with shfl_down at the end.
__global__ void __launch_bounds__(256)
gather64(float* __restrict__ out, int r) {
    int w = (blockIdx.x * blockDim.x + threadIdx.x) >> 5;
    if (w >= NN) return;
    int lane = threadIdx.x & 31;
    int pair = lane >> 4;            // 0 | 1
    int l16  = lane & 15;
    int idx = r * NN + w;
    int beg = g_rowptr[idx];
    int end = (idx == NSC - 1) ? RR * EE : g_rowptr[idx + 1];
    if (beg == end) return;
    const uint2* h = (const uint2*)g_h16;   // 16 uint2 per 64-feat row
    float4 a = make_float4(0.f, 0.f, 0.f, 0.f);
    int n = end - beg;
    while (n > 0) {
        int take = n < 32 ? n : 32;
        int sid = (lane < take) ? g_srt[beg + lane] : 0;
        int j = 0;
        for (; j + 2 <= take; j += 2) {
            int s = __shfl_sync(FULL, sid, j + pair);
            uint2 raw = h[(size_t)s * (FOUT / 4) + l16];
            h4_acc(a, raw);
        }
        if (j < take) {
            int s = __shfl_sync(FULL, sid, j);
            if (pair == 0) {
                uint2 raw = h[(size_t)s * (FOUT / 4) + l16];
                h4_acc(a, raw);
            }
        }
        beg += take;
        n -= take;
    }
    // combine pair-1 partials into pair-0 lanes
    a.x += __shfl_down_sync(FULL, a.x, 16);
    a.y += __shfl_down_sync(FULL, a.y, 16);
    a.z += __shfl_down_sync(FULL, a.z, 16);
    a.w += __shfl_down_sync(FULL, a.w, 16);
    if (pair == 0) {
        float sc = g_dinv_in[idx];
        float4* o4 = (float4*)out;
        size_t o = (size_t)w * (FOUT / 4) + l16;
        float4 cur = o4[o];
        cur.x += sc * a.x;
        cur.y += sc * a.y;
        cur.z += sc * a.z;
        cur.w += sc * a.w;
        o4[o] = cur;
    }
}

// ---------------------------------------------------------------------------
// Launch — only genuine harness pointers cross host/device.
// ---------------------------------------------------------------------------
extern "C" void kernel_launch(void* const* d_in, const int* in_sizes, int n_in,
                              void* d_out, int out_size) {
    const float* x = nullptr; const int* esrc = nullptr; const int* edst = nullptr;
    const float* W1 = nullptr; const float* b1 = nullptr;
    const float* W2 = nullptr; const float* b2 = nullptr;
    for (int i = 0; i < n_in; i++) {
        switch (in_sizes[i]) {
            case NN * FIN:       x  = (const float*)d_in[i]; break;
            case RR * EE:        if (!esrc) esrc = (const int*)d_in[i];
                                 else       edst = (const int*)d_in[i]; break;
            case RR * FIN * FHID:  W1 = (const float*)d_in[i]; break;
            case RR * FHID:        b1 = (const float*)d_in[i]; break;
            case RR * FHID * FOUT: W2 = (const float*)d_in[i]; break;
            case RR * FOUT:        b2 = (const float*)d_in[i]; break;
            default: break;
        }
    }
    if (!x || !esrc || !edst || !W1 || !b1 || !W2 || !b2) {
        x    = (const float*)d_in[0];
        esrc = (const int*)  d_in[1];
        edst = (const int*)  d_in[2];
        W1   = (const float*)d_in[3];
        b1   = (const float*)d_in[4];
        W2   = (const float*)d_in[5];
        b2   = (const float*)d_in[6];
    }
    float* out = (float*)d_out;

    // 1) zero scratch; out <- broadcast sum_r b2[r]
    zero_all<<<2048, 256>>>((float4*)out, b2);

    // 2) degrees -> rsqrt; sb1
    degree_kernel<<<(RR * EE + 255) / 256, 256>>>(esrc, edst);
    rsqrt_kernel<<<(NSC + 255) / 256, 256>>>(b1);

    // 3) CSR build
    scan1<<<NB, 256>>>();
    scan2<<<1, 512>>>();
    scan3<<<NB, 256>>>();
    place_kernel<<<(RR * EE + 255) / 256, 256>>>(esrc, edst);

    dim3 ggrid((NN + 127) / 128, 1, 1);
    int gather_grid = (NN * 32 + 255) / 256;

    // 4) layer 1, per relation (h16 + acc1 L2-resident, no atomics)
    for (int r = 0; r < RR; r++) {
        gemm1_tc<<<ggrid, 256>>>(x, W1, NN, r);
        gather128<<<gather_grid, 256>>>(r);
    }

    // 5) layer 2, per relation, fused relu(acc1 + sb1) at the A-stage
    for (int r = 0; r < RR; r++) {
        gemm2_tc<<<ggrid, 256>>>(W2, NN, r);
        gather64<<<gather_grid, 256>>>(out, r);
    }
}

// round 15
// speedup vs baseline: 1.3258x; 1.3258x over previous
#include <cuda_runtime.h>
#include <cuda_fp16.h>
#include <cstdint>

// Problem constants
#define NN   100000   // nodes
#define RR   4        // relations
#define EE   500000   // edges per relation
#define FIN  256
#define FHID 128
#define FOUT 64

#define NSC  (RR * NN)                   // scan length (400000)
#define NB   ((NSC + 1023) / 1024)       // scan blocks (391)

// ---------------------------------------------------------------------------
// Scratch (static device globals). ONLY referenced from device code — passing
// these symbols as kernel args from host code yields the host-shadow address,
// which GB300 ATS silently dereferences into HOST memory (R5/R6 bug).
// ---------------------------------------------------------------------------
__device__ __align__(256) float  g_dinv_out[RR * NN];            // rsqrt(out-degree)
__device__ __align__(256) float  g_dinv_in [RR * NN];            // rsqrt(in-degree)
__device__ __align__(256) __half g_h16[(size_t)RR * NN * FHID];  // per-relation transforms
__device__ __align__(256) float  g_acc1[(size_t)NN * FHID];      // layer-1 aggregate
__device__ __align__(256) float  g_sb1[FHID];                    // sum_r b1[r]
__device__ __align__(256) float  g_sb2[FOUT];                    // sum_r b2[r]
// CSR build
__device__ __align__(256) int    g_cnt   [NSC];
__device__ __align__(256) int    g_rowptr[NSC];
__device__ __align__(256) int    g_wptr  [NSC];
__device__ __align__(256) int    g_bsum  [512];
__device__ __align__(256) int    g_srt   [RR * EE];              // src ids, dst-sorted

// ---------------------------------------------------------------------------
// Zero only the histogram + out-degree counters (gathers write acc1/out fully)
// ---------------------------------------------------------------------------
__global__ void zero_small() {
    int i = blockIdx.x * blockDim.x + threadIdx.x;
    int stride = gridDim.x * blockDim.x;
    float4* dout4 = (float4*)g_dinv_out;
    int4*   cnt4  = (int4*)g_cnt;
    float4 z = make_float4(0.f, 0.f, 0.f, 0.f);
    int4 zi = make_int4(0, 0, 0, 0);
    for (int j = i; j < NSC / 4; j += stride) { dout4[j] = z; cnt4[j] = zi; }
}

// ---------------------------------------------------------------------------
// Degrees: int histogram on dst (drives dinv_in + CSR), float accum on src
// ---------------------------------------------------------------------------
__global__ void degree_kernel(const int* __restrict__ src, const int* __restrict__ dst) {
    int t = blockIdx.x * blockDim.x + threadIdx.x;
    if (t >= RR * EE) return;
    int r = t / EE;
    atomicAdd(&g_cnt[r * NN + dst[t]], 1);
    atomicAdd(&g_dinv_out[r * NN + src[t]], 1.0f);
}

// rsqrt of degrees + sb1/sb2 bias sums
__global__ void rsqrt_kernel(const float* __restrict__ b1, const float* __restrict__ b2) {
    int t = blockIdx.x * blockDim.x + threadIdx.x;
    if (t < FHID) {
        float s = 0.f;
        #pragma unroll
        for (int r = 0; r < RR; r++) s += b1[r * FHID + t];
        g_sb1[t] = s;
    }
    if (t < FOUT) {
        float s = 0.f;
        #pragma unroll
        for (int r = 0; r < RR; r++) s += b2[r * FOUT + t];
        g_sb2[t] = s;
    }
    if (t >= NSC) return;
    g_dinv_out[t] = rsqrtf(fmaxf(g_dinv_out[t], 1.0f));
    g_dinv_in [t] = rsqrtf(fmaxf((float)g_cnt[t], 1.0f));
}

// ---------------------------------------------------------------------------
// Two-level exclusive scan of g_cnt -> g_rowptr (+ g_wptr copy)
// ---------------------------------------------------------------------------
__global__ void scan1() {
    __shared__ int sh[256];
    int tid = threadIdx.x;
    int i0 = blockIdx.x * 1024 + tid * 4;
    int a0 = (i0 + 0 < NSC) ? g_cnt[i0 + 0] : 0;
    int a1 = (i0 + 1 < NSC) ? g_cnt[i0 + 1] : 0;
    int a2 = (i0 + 2 < NSC) ? g_cnt[i0 + 2] : 0;
    int a3 = (i0 + 3 < NSC) ? g_cnt[i0 + 3] : 0;
    int s0 = a0, s1 = s0 + a1, s2 = s1 + a2, s3 = s2 + a3;
    sh[tid] = s3;
    __syncthreads();
    for (int d = 1; d < 256; d <<= 1) {
        int v = (tid >= d) ? sh[tid - d] : 0;
        __syncthreads();
        sh[tid] += v;
        __syncthreads();
    }
    int ex = sh[tid] - s3;
    if (i0 + 0 < NSC) g_rowptr[i0 + 0] = ex;
    if (i0 + 1 < NSC) g_rowptr[i0 + 1] = ex + s0;
    if (i0 + 2 < NSC) g_rowptr[i0 + 2] = ex + s1;
    if (i0 + 3 < NSC) g_rowptr[i0 + 3] = ex + s2;
    if (tid == 255) g_bsum[blockIdx.x] = sh[255];
}

__global__ void scan2() {
    __shared__ int sh[512];
    int tid = threadIdx.x;
    int v = (tid < NB) ? g_bsum[tid] : 0;
    sh[tid] = v;
    __syncthreads();
    for (int d = 1; d < 512; d <<= 1) {
        int u = (tid >= d) ? sh[tid - d] : 0;
        __syncthreads();
        sh[tid] += u;
        __syncthreads();
    }
    if (tid < NB) g_bsum[tid] = sh[tid] - v;
}

__global__ void scan3() {
    int add = g_bsum[blockIdx.x];
    int i0 = blockIdx.x * 1024 + threadIdx.x * 4;
    #pragma unroll
    for (int j = 0; j < 4; j++) {
        int i = i0 + j;
        if (i < NSC) {
            int v = g_rowptr[i] + add;
            g_rowptr[i] = v;
            g_wptr[i] = v;
        }
    }
}

__global__ void place_kernel(const int* __restrict__ src, const int* __restrict__ dst) {
    int t = blockIdx.x * blockDim.x + threadIdx.x;
    if (t >= RR * EE) return;
    int r = t / EE;
    int pos = atomicAdd(&g_wptr[r * NN + dst[t]], 1);
    g_srt[pos] = src[t];
}

// ---------------------------------------------------------------------------
// TF32 helpers
// ---------------------------------------------------------------------------
__device__ __forceinline__ uint32_t f2tf32(float x) {
    uint32_t u;
    asm("cvt.rna.tf32.f32 %0, %1;" : "=r"(u) : "f"(x));
    return u;
}

__device__ __forceinline__ void mma_tf32(float* c, const uint32_t* a,
                                         uint32_t b0, uint32_t b1) {
    asm volatile(
        "mma.sync.aligned.m16n8k8.row.col.f32.tf32.tf32.f32 "
        "{%0,%1,%2,%3}, {%4,%5,%6,%7}, {%8,%9}, {%0,%1,%2,%3};"
        : "+f"(c[0]), "+f"(c[1]), "+f"(c[2]), "+f"(c[3])
        : "r"(a[0]), "r"(a[1]), "r"(a[2]), "r"(a[3]), "r"(b0), "r"(b1));
}

// ---------------------------------------------------------------------------
// Register-staged TF32 GEMM (R11/R12-validated body), ALL relations in one
// launch via blockIdx.z = r. Writes g_h16 + r*NN*BN (fp16):
//   h[r][m][n] = half( dinv_out[r][m] * sum_k f(A[m][k]) * W[r][k][n] )
// LAYER2: A = g_acc1, f(a) = relu(a + g_sb1[k]); else A = A_in (x).
// ---------------------------------------------------------------------------
template <int BN, bool LAYER2>
__global__ void __launch_bounds__(256, 2)
gemm_tc(const float* __restrict__ A_in,
        const float* __restrict__ W,
        int M, int K)
{
    constexpr int BM = 128, BK = 32;
    constexpr int APT  = BM * BK / 4 / 256;
    constexpr int BPT  = BK * BN / 4 / 256;
    constexpr int ASTR = BK + 4;
    constexpr int BSTR = BN + 8;
    constexpr int WN   = BN / 2;
    constexpr int NT   = WN / 8;

    __shared__ uint32_t As[BM * ASTR];
    __shared__ uint32_t Bs[BK * BSTR];

    const int r = blockIdx.z;
    const float* A = LAYER2 ? g_acc1 : A_in;
    const float* B = W + (size_t)r * K * BN;
    __half* H = g_h16 + (size_t)r * NN * BN;

    const int tid  = threadIdx.x;
    const int wid  = tid >> 5;
    const int lane = tid & 31;
    const int g    = lane >> 2;
    const int tig  = lane & 3;
    const int warp_m = wid & 3;
    const int warp_n = wid >> 2;
    const int rowBase = blockIdx.x * BM;

    float acc[2][NT][4];
    #pragma unroll
    for (int mt = 0; mt < 2; mt++)
        #pragma unroll
        for (int nt = 0; nt < NT; nt++)
            #pragma unroll
            for (int j = 0; j < 4; j++) acc[mt][nt][j] = 0.f;

    float4 aReg[APT], bReg[BPT];

    auto load_regs = [&](int k0) {
        #pragma unroll
        for (int i = 0; i < APT; i++) {
            int f = i * 256 + tid;
            int ar = f >> 3;
            int ac = f & 7;
            int grow = rowBase + ar;
            float4 v = make_float4(0.f, 0.f, 0.f, 0.f);
            if (grow < M)
                v = *(const float4*)(A + (size_t)grow * K + k0 + ac * 4);
            aReg[i] = v;
        }
        #pragma unroll
        for (int i = 0; i < BPT; i++) {
            int f = i * 256 + tid;
            int br = f / (BN / 4);
            int bc = f % (BN / 4);
            bReg[i] = *(const float4*)(B + (size_t)(k0 + br) * BN + bc * 4);
        }
    };

    auto store_smem = [&](int kload) {
        #pragma unroll
        for (int i = 0; i < APT; i++) {
            int f = i * 256 + tid;
            int ar = f >> 3;
            int ac = f & 7;
            float4 v = aReg[i];
            if (LAYER2) {
                const float* bb = g_sb1 + kload + ac * 4;
                v.x = fmaxf(v.x + bb[0], 0.f);
                v.y = fmaxf(v.y + bb[1], 0.f);
                v.z = fmaxf(v.z + bb[2], 0.f);
                v.w = fmaxf(v.w + bb[3], 0.f);
            }
            uint4 u = make_uint4(f2tf32(v.x), f2tf32(v.y), f2tf32(v.z), f2tf32(v.w));
            *(uint4*)&As[ar * ASTR + ac * 4] = u;
        }
        #pragma unroll
        for (int i = 0; i < BPT; i++) {
            int f = i * 256 + tid;
            int br = f / (BN / 4);
            int bc = f % (BN / 4);
            float4 v = bReg[i];
            uint4 u = make_uint4(f2tf32(v.x), f2tf32(v.y), f2tf32(v.z), f2tf32(v.w));
            *(uint4*)&Bs[br * BSTR + bc * 4] = u;
        }
    };

    auto compute = [&]() {
        #pragma unroll
        for (int ks = 0; ks < 4; ks++) {
            int k8 = ks * 8;
            uint32_t a[2][4];
            #pragma unroll
            for (int mt = 0; mt < 2; mt++) {
                int rb = warp_m * 32 + mt * 16;
                a[mt][0] = As[(rb + g)     * ASTR + k8 + tig];
                a[mt][1] = As[(rb + g + 8) * ASTR + k8 + tig];
                a[mt][2] = As[(rb + g)     * ASTR + k8 + tig + 4];
                a[mt][3] = As[(rb + g + 8) * ASTR + k8 + tig + 4];
            }
            #pragma unroll
            for (int nt = 0; nt < NT; nt++) {
                int cb = warp_n * WN + nt * 8;
                uint32_t b0 = Bs[(k8 + tig)     * BSTR + cb + g];
                uint32_t b1 = Bs[(k8 + tig + 4) * BSTR + cb + g];
                #pragma unroll
                for (int mt = 0; mt < 2; mt++)
                    mma_tf32(acc[mt][nt], a[mt], b0, b1);
            }
        }
    };

    load_regs(0);
    store_smem(0);
    __syncthreads();
    for (int k0 = BK; k0 < K; k0 += BK) {
        load_regs(k0);
        compute();
        __syncthreads();
        store_smem(k0);
        __syncthreads();
    }
    compute();

    #pragma unroll
    for (int mt = 0; mt < 2; mt++) {
        int row0 = rowBase + warp_m * 32 + mt * 16 + g;
        int row1 = row0 + 8;
        float s0 = (row0 < M) ? g_dinv_out[(size_t)r * NN + row0] : 0.f;
        float s1 = (row1 < M) ? g_dinv_out[(size_t)r * NN + row1] : 0.f;
        #pragma unroll
        for (int nt = 0; nt < NT; nt++) {
            int col = warp_n * WN + nt * 8 + 2 * tig;
            if (row0 < M)
                *(__half2*)&H[(size_t)row0 * BN + col] =
                    __floats2half2_rn(acc[mt][nt][0] * s0, acc[mt][nt][1] * s0);
            if (row1 < M)
                *(__half2*)&H[(size_t)row1 * BN + col] =
                    __floats2half2_rn(acc[mt][nt][2] * s1, acc[mt][nt][3] * s1);
        }
    }
}

// ---------------------------------------------------------------------------
// CSR gather-aggregation, no atomics, ALL relations per warp (R12-validated
// inner loop: broadcast id loads + dual accumulator). One warp owns one dst;
// accumulator written ONCE (write-only; no zero-init needed).
// ---------------------------------------------------------------------------
__device__ __forceinline__ void h4_acc(float4& a, uint2 raw) {
    float2 f01 = __half22float2(*(__half2*)&raw.x);
    float2 f23 = __half22float2(*(__half2*)&raw.y);
    a.x += f01.x; a.y += f01.y; a.z += f23.x; a.w += f23.y;
}

// Layer 1: acc1[d] = sum_r dinv_in[r][d] * sum_{e in CSR_r[d]} h1[r][src_e]
__global__ void __launch_bounds__(256)
gather128_all() {
    int w = (blockIdx.x * blockDim.x + threadIdx.x) >> 5;
    if (w >= NN) return;
    int lane = threadIdx.x & 31;
    const uint2* h = (const uint2*)g_h16;
    float4 tot = make_float4(0.f, 0.f, 0.f, 0.f);
    #pragma unroll
    for (int r = 0; r < RR; r++) {
        int idx = r * NN + w;
        int beg = g_rowptr[idx];
        int end = (idx == NSC - 1) ? RR * EE : g_rowptr[idx + 1];
        if (beg == end) continue;
        float4 a0 = make_float4(0.f, 0.f, 0.f, 0.f);
        float4 a1 = make_float4(0.f, 0.f, 0.f, 0.f);
        size_t rbase = (size_t)r * NN;
        int e = beg;
        for (; e + 2 <= end; e += 2) {
            int s0 = g_srt[e], s1 = g_srt[e + 1];
            uint2 r0 = h[(rbase + s0) * (FHID / 4) + lane];
            uint2 r1 = h[(rbase + s1) * (FHID / 4) + lane];
            h4_acc(a0, r0);
            h4_acc(a1, r1);
        }
        if (e < end) {
            uint2 r0 = h[(rbase + g_srt[e]) * (FHID / 4) + lane];
            h4_acc(a0, r0);
        }
        float sc = g_dinv_in[idx];
        tot.x += sc * (a0.x + a1.x);
        tot.y += sc * (a0.y + a1.y);
        tot.z += sc * (a0.z + a1.z);
        tot.w += sc * (a0.w + a1.w);
    }
    ((float4*)g_acc1)[(size_t)w * (FHID / 4) + lane] = tot;   // write-only
}

// Layer 2: out[d] = sb2 + sum_r dinv_in[r][d] * sum_e h2[r][src_e]
// lane handles one half2 (2 feats); h2[r] lives at g_h16 + r*NN*FOUT.
__global__ void __launch_bounds__(256)
gather64_all(float* __restrict__ out) {
    int w = (blockIdx.x * blockDim.x + threadIdx.x) >> 5;
    if (w >= NN) return;
    int lane = threadIdx.x & 31;
    const uint32_t* h = (const uint32_t*)g_h16;
    float2 tot = make_float2(g_sb2[2 * lane], g_sb2[2 * lane + 1]);
    #pragma unroll
    for (int r = 0; r < RR; r++) {
        int idx = r * NN + w;
        int beg = g_rowptr[idx];
        int end = (idx == NSC - 1) ? RR * EE : g_rowptr[idx + 1];
        if (beg == end) continue;
        float2 a0 = make_float2(0.f, 0.f);
        float2 a1 = make_float2(0.f, 0.f);
        size_t rbase = (size_t)r * NN;
        int e = beg;
        for (; e + 2 <= end; e += 2) {
            uint32_t r0 = h[(rbase + g_srt[e])     * (FOUT / 2) + lane];
            uint32_t r1 = h[(rbase + g_srt[e + 1]) * (FOUT / 2) + lane];
            float2 f0 = __half22float2(*(__half2*)&r0);
            float2 f1 = __half22float2(*(__half2*)&r1);
            a0.x += f0.x; a0.y += f0.y;
            a1.x += f1.x; a1.y += f1.y;
        }
        if (e < end) {
            uint32_t r0 = h[(rbase + g_srt[e]) * (FOUT / 2) + lane];
            float2 f0 = __half22float2(*(__half2*)&r0);
            a0.x += f0.x; a0.y += f0.y;
        }
        float sc = g_dinv_in[idx];
        tot.x += sc * (a0.x + a1.x);
        tot.y += sc * (a0.y + a1.y);
    }
    ((float2*)out)[(size_t)w * (FOUT / 2) + lane] = tot;      // write-only (bias included)
}

// ---------------------------------------------------------------------------
// Launch — only genuine harness pointers cross host/device.
// ---------------------------------------------------------------------------
extern "C" void kernel_launch(void* const* d_in, const int* in_sizes, int n_in,
                              void* d_out, int out_size) {
    const float* x = nullptr; const int* esrc = nullptr; const int* edst = nullptr;
    const float* W1 = nullptr; const float* b1 = nullptr;
    const float* W2 = nullptr; const float* b2 = nullptr;
    for (int i = 0; i < n_in; i++) {
        switch (in_sizes[i]) {
            case NN * FIN:       x  = (const float*)d_in[i]; break;
            case RR * EE:        if (!esrc) esrc = (const int*)d_in[i];
                                 else       edst = (const int*)d_in[i]; break;
            case RR * FIN * FHID:  W1 = (const float*)d_in[i]; break;
            case RR * FHID:        b1 = (const float*)d_in[i]; break;
            case RR * FHID * FOUT: W2 = (const float*)d_in[i]; break;
            case RR * FOUT:        b2 = (const float*)d_in[i]; break;
            default: break;
        }
    }
    if (!x || !esrc || !edst || !W1 || !b1 || !W2 || !b2) {
        x    = (const float*)d_in[0];
        esrc = (const int*)  d_in[1];
        edst = (const int*)  d_in[2];
        W1   = (const float*)d_in[3];
        b1   = (const float*)d_in[4];
        W2   = (const float*)d_in[5];
        b2   = (const float*)d_in[6];
    }
    float* out = (float*)d_out;

    // 1) zero histogram + out-degree counters only
    zero_small<<<512, 256>>>();

    // 2) degrees -> rsqrt; bias sums
    degree_kernel<<<(RR * EE + 255) / 256, 256>>>(esrc, edst);
    rsqrt_kernel<<<(NSC + 255) / 256, 256>>>(b1, b2);

    // 3) CSR build
    scan1<<<NB, 256>>>();
    scan2<<<1, 512>>>();
    scan3<<<NB, 256>>>();
    place_kernel<<<(RR * EE + 255) / 256, 256>>>(esrc, edst);

    dim3 ggrid((NN + 127) / 128, 1, RR);          // all relations in one launch
    int gather_grid = (NN * 32 + 255) / 256;

    // 4) layer 1: h1[r] = dinv_out (x @ W1[r]); acc1 = sum_r dinv_in * gather(h1[r])
    gemm_tc<FHID, false><<<ggrid, 256>>>(x, W1, NN, FIN);
    gather128_all<<<gather_grid, 256>>>();

    // 5) layer 2: h2[r] = dinv_out (relu(acc1+sb1) @ W2[r]); out = sb2 + sum_r gather
    gemm_tc<FOUT, true><<<ggrid, 256>>>(nullptr, W2, NN, FHID);
    gather64_all<<<gather_grid, 256>>>(out);
}

// round 17
// speedup vs baseline: 1.4716x; 1.1100x over previous
#include <cuda_runtime.h>
#include <cuda_fp16.h>
#include <cstdint>

// Problem constants
#define NN   100000   // nodes
#define RR   4        // relations
#define EE   500000   // edges per relation
#define FIN  256
#define FHID 128
#define FOUT 64

#define NSC  (RR * NN)                   // scan length (400000)
#define NB   ((NSC + 1023) / 1024)       // scan blocks (391)

// ---------------------------------------------------------------------------
// Scratch (static device globals). ONLY referenced from device code — passing
// these symbols as kernel args from host code yields the host-shadow address,
// which GB300 ATS silently dereferences into HOST memory (R5/R6 bug).
// ---------------------------------------------------------------------------
__device__ __align__(256) float  g_dinv_out[RR * NN];            // rsqrt(out-degree)
__device__ __align__(256) float  g_dinv_in [RR * NN];            // rsqrt(in-degree)
__device__ __align__(256) __half g_h16[(size_t)RR * NN * FHID];  // per-relation transforms
__device__ __align__(256) float  g_acc1[(size_t)NN * FHID];      // layer-1 aggregate
__device__ __align__(256) float  g_sb1[FHID];                    // sum_r b1[r]
__device__ __align__(256) float  g_sb2[FOUT];                    // sum_r b2[r]
__device__ __align__(256) __half g_x16[(size_t)NN * FIN];        // x in fp16 (rn)
__device__ __align__(256) __half g_w116[(size_t)RR * FHID * FIN];// W1 fp16, [R][N][K]
// CSR build
__device__ __align__(256) int    g_cnt   [NSC];
__device__ __align__(256) int    g_rowptr[NSC];
__device__ __align__(256) int    g_wptr  [NSC];
__device__ __align__(256) int    g_bsum  [512];
__device__ __align__(256) int    g_srt   [RR * EE];              // src ids, dst-sorted

// ---------------------------------------------------------------------------
// Zero only the histogram + out-degree counters (gathers write acc1/out fully)
// ---------------------------------------------------------------------------
__global__ void zero_small() {
    int i = blockIdx.x * blockDim.x + threadIdx.x;
    int stride = gridDim.x * blockDim.x;
    float4* dout4 = (float4*)g_dinv_out;
    int4*   cnt4  = (int4*)g_cnt;
    float4 z = make_float4(0.f, 0.f, 0.f, 0.f);
    int4 zi = make_int4(0, 0, 0, 0);
    for (int j = i; j < NSC / 4; j += stride) { dout4[j] = z; cnt4[j] = zi; }
}

// ---------------------------------------------------------------------------
// Pre-convert x -> fp16 (rn) and W1 -> fp16 transposed [R][N][K]
// ---------------------------------------------------------------------------
__global__ void convert_x(const float* __restrict__ x) {
    int i = blockIdx.x * blockDim.x + threadIdx.x;
    int stride = gridDim.x * blockDim.x;
    const float4* x4 = (const float4*)x;
    uint2* o = (uint2*)g_x16;
    for (int j = i; j < (NN * FIN) / 4; j += stride) {
        float4 v = x4[j];
        __half2 h01 = __floats2half2_rn(v.x, v.y);
        __half2 h23 = __floats2half2_rn(v.z, v.w);
        uint2 u;
        u.x = *(uint32_t*)&h01;
        u.y = *(uint32_t*)&h23;
        o[j] = u;
    }
}

__global__ void convert_w1(const float* __restrict__ W1) {
    int t = blockIdx.x * blockDim.x + threadIdx.x;
    if (t >= RR * FIN * FHID) return;
    int r = t / (FIN * FHID);
    int rem = t % (FIN * FHID);
    int k = rem / FHID;
    int n = rem % FHID;
    g_w116[((size_t)r * FHID + n) * FIN + k] = __float2half_rn(W1[t]);
}

// ---------------------------------------------------------------------------
// Degrees: int histogram on dst (drives dinv_in + CSR), float accum on src
// ---------------------------------------------------------------------------
__global__ void degree_kernel(const int* __restrict__ src, const int* __restrict__ dst) {
    int t = blockIdx.x * blockDim.x + threadIdx.x;
    if (t >= RR * EE) return;
    int r = t / EE;
    atomicAdd(&g_cnt[r * NN + dst[t]], 1);
    atomicAdd(&g_dinv_out[r * NN + src[t]], 1.0f);
}

// rsqrt of degrees + sb1/sb2 bias sums
__global__ void rsqrt_kernel(const float* __restrict__ b1, const float* __restrict__ b2) {
    int t = blockIdx.x * blockDim.x + threadIdx.x;
    if (t < FHID) {
        float s = 0.f;
        #pragma unroll
        for (int r = 0; r < RR; r++) s += b1[r * FHID + t];
        g_sb1[t] = s;
    }
    if (t < FOUT) {
        float s = 0.f;
        #pragma unroll
        for (int r = 0; r < RR; r++) s += b2[r * FOUT + t];
        g_sb2[t] = s;
    }
    if (t >= NSC) return;
    g_dinv_out[t] = rsqrtf(fmaxf(g_dinv_out[t], 1.0f));
    g_dinv_in [t] = rsqrtf(fmaxf((float)g_cnt[t], 1.0f));
}

// ---------------------------------------------------------------------------
// Two-level exclusive scan of g_cnt -> g_rowptr (+ g_wptr copy)
// ---------------------------------------------------------------------------
__global__ void scan1() {
    __shared__ int sh[256];
    int tid = threadIdx.x;
    int i0 = blockIdx.x * 1024 + tid * 4;
    int a0 = (i0 + 0 < NSC) ? g_cnt[i0 + 0] : 0;
    int a1 = (i0 + 1 < NSC) ? g_cnt[i0 + 1] : 0;
    int a2 = (i0 + 2 < NSC) ? g_cnt[i0 + 2] : 0;
    int a3 = (i0 + 3 < NSC) ? g_cnt[i0 + 3] : 0;
    int s0 = a0, s1 = s0 + a1, s2 = s1 + a2, s3 = s2 + a3;
    sh[tid] = s3;
    __syncthreads();
    for (int d = 1; d < 256; d <<= 1) {
        int v = (tid >= d) ? sh[tid - d] : 0;
        __syncthreads();
        sh[tid] += v;
        __syncthreads();
    }
    int ex = sh[tid] - s3;
    if (i0 + 0 < NSC) g_rowptr[i0 + 0] = ex;
    if (i0 + 1 < NSC) g_rowptr[i0 + 1] = ex + s0;
    if (i0 + 2 < NSC) g_rowptr[i0 + 2] = ex + s1;
    if (i0 + 3 < NSC) g_rowptr[i0 + 3] = ex + s2;
    if (tid == 255) g_bsum[blockIdx.x] = sh[255];
}

__global__ void scan2() {
    __shared__ int sh[512];
    int tid = threadIdx.x;
    int v = (tid < NB) ? g_bsum[tid] : 0;
    sh[tid] = v;
    __syncthreads();
    for (int d = 1; d < 512; d <<= 1) {
        int u = (tid >= d) ? sh[tid - d] : 0;
        __syncthreads();
        sh[tid] += u;
        __syncthreads();
    }
    if (tid < NB) g_bsum[tid] = sh[tid] - v;
}

__global__ void scan3() {
    int add = g_bsum[blockIdx.x];
    int i0 = blockIdx.x * 1024 + threadIdx.x * 4;
    #pragma unroll
    for (int j = 0; j < 4; j++) {
        int i = i0 + j;
        if (i < NSC) {
            int v = g_rowptr[i] + add;
            g_rowptr[i] = v;
            g_wptr[i] = v;
        }
    }
}

__global__ void place_kernel(const int* __restrict__ src, const int* __restrict__ dst) {
    int t = blockIdx.x * blockDim.x + threadIdx.x;
    if (t >= RR * EE) return;
    int r = t / EE;
    int pos = atomicAdd(&g_wptr[r * NN + dst[t]], 1);
    g_srt[pos] = src[t];
}

// ---------------------------------------------------------------------------
// MMA / cp.async helpers
// ---------------------------------------------------------------------------
__device__ __forceinline__ uint32_t f2tf32(float x) {
    uint32_t u;
    asm("cvt.rna.tf32.f32 %0, %1;" : "=r"(u) : "f"(x));
    return u;
}

__device__ __forceinline__ void mma_tf32(float* c, const uint32_t* a,
                                         uint32_t b0, uint32_t b1) {
    asm volatile(
        "mma.sync.aligned.m16n8k8.row.col.f32.tf32.tf32.f32 "
        "{%0,%1,%2,%3}, {%4,%5,%6,%7}, {%8,%9}, {%0,%1,%2,%3};"
        : "+f"(c[0]), "+f"(c[1]), "+f"(c[2]), "+f"(c[3])
        : "r"(a[0]), "r"(a[1]), "r"(a[2]), "r"(a[3]), "r"(b0), "r"(b1));
}

__device__ __forceinline__ void mma_f16(float* c, const uint32_t* a,
                                        uint32_t b0, uint32_t b1) {
    asm volatile(
        "mma.sync.aligned.m16n8k16.row.col.f32.f16.f16.f32 "
        "{%0,%1,%2,%3}, {%4,%5,%6,%7}, {%8,%9}, {%0,%1,%2,%3};"
        : "+f"(c[0]), "+f"(c[1]), "+f"(c[2]), "+f"(c[3])
        : "r"(a[0]), "r"(a[1]), "r"(a[2]), "r"(a[3]), "r"(b0), "r"(b1));
}

__device__ __forceinline__ void cp16(uint32_t smem, const void* g, int srcbytes) {
    asm volatile("cp.async.cg.shared.global [%0], [%1], 16, %2;"
                 :: "r"(smem), "l"(g), "r"(srcbytes));
}
__device__ __forceinline__ void cp_commit() {
    asm volatile("cp.async.commit_group;");
}
template <int N>
__device__ __forceinline__ void cp_wait() {
    asm volatile("cp.async.wait_group %0;" :: "n"(N));
}

// ---------------------------------------------------------------------------
// Layer-1 GEMM: fp16 m16n8k16, cp.async double-buffered, all relations via
// blockIdx.z. Operands pre-converted (rn): g_x16 [M][K], g_w116 [R][N][K].
//   g_h16[r][m][n] = half( dinv_out[r][m] * sum_k x16[m][k] * w116[r][n][k] )
// BM=128, BN=128, BK=32, 2 stages x 20KB smem, 256 threads = 8 warps (4m x 2n).
// Smem strides 40 halfs (20 words): A-frag bank = (20g + tig) % 32 — all 32
// distinct; same for B ([n][k] layout feeds col-major B directly).
// ---------------------------------------------------------------------------
__global__ void __launch_bounds__(256)
gemm1_f16(int M)
{
    constexpr int BM = 128, BN = 128, BK = 32, KT = FIN / BK;  // 8 k-tiles
    constexpr int ASTR = BK + 8;      // 40 halfs
    constexpr int BSTR = BK + 8;      // 40 halfs
    constexpr int WN = BN / 2, NT = WN / 8;

    __shared__ __half As[2][BM * ASTR];
    __shared__ __half Bs[2][BN * BSTR];

    const int r = blockIdx.z;
    const __half* A = g_x16;
    const __half* B = g_w116 + (size_t)r * FHID * FIN;   // [n][k]
    __half* H = g_h16 + (size_t)r * NN * FHID;

    const int tid  = threadIdx.x;
    const int wid  = tid >> 5;
    const int lane = tid & 31;
    const int g    = lane >> 2;
    const int tig  = lane & 3;
    const int warp_m = wid & 3;
    const int warp_n = wid >> 2;
    const int rowBase = blockIdx.x * BM;

    float acc[2][NT][4];
    #pragma unroll
    for (int mt = 0; mt < 2; mt++)
        #pragma unroll
        for (int nt = 0; nt < NT; nt++)
            #pragma unroll
            for (int j = 0; j < 4; j++) acc[mt][nt][j] = 0.f;

    // tiles: 128 rows x 32 halfs = 4 x 16B chunks per row -> 512 chunks, 2/thread
    auto load_stage = [&](int s, int k0) {
        #pragma unroll
        for (int i = 0; i < 2; i++) {
            int f = i * 256 + tid;
            int ar = f >> 2;
            int ac = f & 3;
            int grow = rowBase + ar;
            const __half* gp = A + (size_t)(grow < M ? grow : 0) * FIN + k0 + ac * 8;
            uint32_t sm = (uint32_t)__cvta_generic_to_shared(&As[s][ar * ASTR + ac * 8]);
            cp16(sm, gp, grow < M ? 16 : 0);
        }
        #pragma unroll
        for (int i = 0; i < 2; i++) {
            int f = i * 256 + tid;
            int br = f >> 2;
            int bc = f & 3;
            const __half* gp = B + (size_t)br * FIN + k0 + bc * 8;
            uint32_t sm = (uint32_t)__cvta_generic_to_shared(&Bs[s][br * BSTR + bc * 8]);
            cp16(sm, gp, 16);
        }
    };

    auto compute = [&](int s) {
        const uint32_t* Aw = (const uint32_t*)&As[s][0];
        const uint32_t* Bw = (const uint32_t*)&Bs[s][0];
        #pragma unroll
        for (int ks = 0; ks < 2; ks++) {            // two k16 steps per BK=32
            int kw = ks * 8;                        // word offset
            uint32_t a[2][4];
            #pragma unroll
            for (int mt = 0; mt < 2; mt++) {
                int rb = warp_m * 32 + mt * 16;
                a[mt][0] = Aw[(rb + g)     * (ASTR / 2) + kw + tig];
                a[mt][1] = Aw[(rb + g + 8) * (ASTR / 2) + kw + tig];
                a[mt][2] = Aw[(rb + g)     * (ASTR / 2) + kw + tig + 4];
                a[mt][3] = Aw[(rb + g + 8) * (ASTR / 2) + kw + tig + 4];
            }
            #pragma unroll
            for (int nt = 0; nt < NT; nt++) {
                int cb = warp_n * WN + nt * 8;
                uint32_t b0 = Bw[(cb + g) * (BSTR / 2) + kw + tig];
                uint32_t b1 = Bw[(cb + g) * (BSTR / 2) + kw + tig + 4];
                #pragma unroll
                for (int mt = 0; mt < 2; mt++)
                    mma_f16(acc[mt][nt], a[mt], b0, b1);
            }
        }
    };

    load_stage(0, 0);
    cp_commit();
    for (int it = 0; it < KT; it++) {
        if (it + 1 < KT) {
            load_stage((it + 1) & 1, (it + 1) * BK);
            cp_commit();
            cp_wait<1>();
        } else {
            cp_wait<0>();
        }
        __syncthreads();
        compute(it & 1);
        __syncthreads();
    }

    // epilogue: scale by dinv_out, store fp16
    #pragma unroll
    for (int mt = 0; mt < 2; mt++) {
        int row0 = rowBase + warp_m * 32 + mt * 16 + g;
        int row1 = row0 + 8;
        float s0 = (row0 < M) ? g_dinv_out[(size_t)r * NN + row0] : 0.f;
        float s1 = (row1 < M) ? g_dinv_out[(size_t)r * NN + row1] : 0.f;
        #pragma unroll
        for (int nt = 0; nt < NT; nt++) {
            int col = warp_n * WN + nt * 8 + 2 * tig;
            if (row0 < M)
                *(__half2*)&H[(size_t)row0 * FHID + col] =
                    __floats2half2_rn(acc[mt][nt][0] * s0, acc[mt][nt][1] * s0);
            if (row1 < M)
                *(__half2*)&H[(size_t)row1 * FHID + col] =
                    __floats2half2_rn(acc[mt][nt][2] * s1, acc[mt][nt][3] * s1);
        }
    }
}

// ---------------------------------------------------------------------------
// Layer-2 GEMM: register-staged TF32 (validated R11-R15 body), all relations
// via blockIdx.z; fused relu(acc1 + sb1) on the A-load.
// ---------------------------------------------------------------------------
template <int BN>
__global__ void __launch_bounds__(256, 2)
gemm2_tc(const float* __restrict__ W, int M, int K)
{
    constexpr int BM = 128, BK = 32;
    constexpr int APT  = BM * BK / 4 / 256;
    constexpr int BPT  = BK * BN / 4 / 256;
    constexpr int ASTR = BK + 4;
    constexpr int BSTR = BN + 8;
    constexpr int WN   = BN / 2;
    constexpr int NT   = WN / 8;

    __shared__ uint32_t As[BM * ASTR];
    __shared__ uint32_t Bs[BK * BSTR];

    const int r = blockIdx.z;
    const float* A = g_acc1;
    const float* B = W + (size_t)r * K * BN;
    __half* H = g_h16 + (size_t)r * NN * BN;

    const int tid  = threadIdx.x;
    const int wid  = tid >> 5;
    const int lane = tid & 31;
    const int g    = lane >> 2;
    const int tig  = lane & 3;
    const int warp_m = wid & 3;
    const int warp_n = wid >> 2;
    const int rowBase = blockIdx.x * BM;

    float acc[2][NT][4];
    #pragma unroll
    for (int mt = 0; mt < 2; mt++)
        #pragma unroll
        for (int nt = 0; nt < NT; nt++)
            #pragma unroll
            for (int j = 0; j < 4; j++) acc[mt][nt][j] = 0.f;

    float4 aReg[APT], bReg[BPT];

    auto load_regs = [&](int k0) {
        #pragma unroll
        for (int i = 0; i < APT; i++) {
            int f = i * 256 + tid;
            int ar = f >> 3;
            int ac = f & 7;
            int grow = rowBase + ar;
            float4 v = make_float4(0.f, 0.f, 0.f, 0.f);
            if (grow < M)
                v = *(const float4*)(A + (size_t)grow * K + k0 + ac * 4);
            aReg[i] = v;
        }
        #pragma unroll
        for (int i = 0; i < BPT; i++) {
            int f = i * 256 + tid;
            int br = f / (BN / 4);
            int bc = f % (BN / 4);
            bReg[i] = *(const float4*)(B + (size_t)(k0 + br) * BN + bc * 4);
        }
    };

    auto store_smem = [&](int kload) {
        #pragma unroll
        for (int i = 0; i < APT; i++) {
            int f = i * 256 + tid;
            int ar = f >> 3;
            int ac = f & 7;
            float4 v = aReg[i];
            const float* bb = g_sb1 + kload + ac * 4;
            v.x = fmaxf(v.x + bb[0], 0.f);
            v.y = fmaxf(v.y + bb[1], 0.f);
            v.z = fmaxf(v.z + bb[2], 0.f);
            v.w = fmaxf(v.w + bb[3], 0.f);
            uint4 u = make_uint4(f2tf32(v.x), f2tf32(v.y), f2tf32(v.z), f2tf32(v.w));
            *(uint4*)&As[ar * ASTR + ac * 4] = u;
        }
        #pragma unroll
        for (int i = 0; i < BPT; i++) {
            int f = i * 256 + tid;
            int br = f / (BN / 4);
            int bc = f % (BN / 4);
            float4 v = bReg[i];
            uint4 u = make_uint4(f2tf32(v.x), f2tf32(v.y), f2tf32(v.z), f2tf32(v.w));
            *(uint4*)&Bs[br * BSTR + bc * 4] = u;
        }
    };

    auto compute = [&]() {
        #pragma unroll
        for (int ks = 0; ks < 4; ks++) {
            int k8 = ks * 8;
            uint32_t a[2][4];
            #pragma unroll
            for (int mt = 0; mt < 2; mt++) {
                int rb = warp_m * 32 + mt * 16;
                a[mt][0] = As[(rb + g)     * ASTR + k8 + tig];
                a[mt][1] = As[(rb + g + 8) * ASTR + k8 + tig];
                a[mt][2] = As[(rb + g)     * ASTR + k8 + tig + 4];
                a[mt][3] = As[(rb + g + 8) * ASTR + k8 + tig + 4];
            }
            #pragma unroll
            for (int nt = 0; nt < NT; nt++) {
                int cb = warp_n * WN + nt * 8;
                uint32_t b0 = Bs[(k8 + tig)     * BSTR + cb + g];
                uint32_t b1 = Bs[(k8 + tig + 4) * BSTR + cb + g];
                #pragma unroll
                for (int mt = 0; mt < 2; mt++)
                    mma_tf32(acc[mt][nt], a[mt], b0, b1);
            }
        }
    };

    load_regs(0);
    store_smem(0);
    __syncthreads();
    for (int k0 = BK; k0 < K; k0 += BK) {
        load_regs(k0);
        compute();
        __syncthreads();
        store_smem(k0);
        __syncthreads();
    }
    compute();

    #pragma unroll
    for (int mt = 0; mt < 2; mt++) {
        int row0 = rowBase + warp_m * 32 + mt * 16 + g;
        int row1 = row0 + 8;
        float s0 = (row0 < M) ? g_dinv_out[(size_t)r * NN + row0] : 0.f;
        float s1 = (row1 < M) ? g_dinv_out[(size_t)r * NN + row1] : 0.f;
        #pragma unroll
        for (int nt = 0; nt < NT; nt++) {
            int col = warp_n * WN + nt * 8 + 2 * tig;
            if (row0 < M)
                *(__half2*)&H[(size_t)row0 * BN + col] =
                    __floats2half2_rn(acc[mt][nt][0] * s0, acc[mt][nt][1] * s0);
            if (row1 < M)
                *(__half2*)&H[(size_t)row1 * BN + col] =
                    __floats2half2_rn(acc[mt][nt][2] * s1, acc[mt][nt][3] * s1);
        }
    }
}

// ---------------------------------------------------------------------------
// CSR gather-aggregation (validated R15 bodies, untouched)
// ---------------------------------------------------------------------------
__device__ __forceinline__ void h4_acc(float4& a, uint2 raw) {
    float2 f01 = __half22float2(*(__half2*)&raw.x);
    float2 f23 = __half22float2(*(__half2*)&raw.y);
    a.x += f01.x; a.y += f01.y; a.z += f23.x; a.w += f23.y;
}

__global__ void __launch_bounds__(256)
gather128_all() {
    int w = (blockIdx.x * blockDim.x + threadIdx.x) >> 5;
    if (w >= NN) return;
    int lane = threadIdx.x & 31;
    const uint2* h = (const uint2*)g_h16;
    float4 tot = make_float4(0.f, 0.f, 0.f, 0.f);
    #pragma unroll
    for (int r = 0; r < RR; r++) {
        int idx = r * NN + w;
        int beg = g_rowptr[idx];
        int end = (idx == NSC - 1) ? RR * EE : g_rowptr[idx + 1];
        if (beg == end) continue;
        float4 a0 = make_float4(0.f, 0.f, 0.f, 0.f);
        float4 a1 = make_float4(0.f, 0.f, 0.f, 0.f);
        size_t rbase = (size_t)r * NN;
        int e = beg;
        for (; e + 2 <= end; e += 2) {
            int s0 = g_srt[e], s1 = g_srt[e + 1];
            uint2 r0 = h[(rbase + s0) * (FHID / 4) + lane];
            uint2 r1 = h[(rbase + s1) * (FHID / 4) + lane];
            h4_acc(a0, r0);
            h4_acc(a1, r1);
        }
        if (e < end) {
            uint2 r0 = h[(rbase + g_srt[e]) * (FHID / 4) + lane];
            h4_acc(a0, r0);
        }
        float sc = g_dinv_in[idx];
        tot.x += sc * (a0.x + a1.x);
        tot.y += sc * (a0.y + a1.y);
        tot.z += sc * (a0.z + a1.z);
        tot.w += sc * (a0.w + a1.w);
    }
    ((float4*)g_acc1)[(size_t)w * (FHID / 4) + lane] = tot;   // write-only
}

__global__ void __launch_bounds__(256)
gather64_all(float* __restrict__ out) {
    int w = (blockIdx.x * blockDim.x + threadIdx.x) >> 5;
    if (w >= NN) return;
    int lane = threadIdx.x & 31;
    const uint32_t* h = (const uint32_t*)g_h16;
    float2 tot = make_float2(g_sb2[2 * lane], g_sb2[2 * lane + 1]);
    #pragma unroll
    for (int r = 0; r < RR; r++) {
        int idx = r * NN + w;
        int beg = g_rowptr[idx];
        int end = (idx == NSC - 1) ? RR * EE : g_rowptr[idx + 1];
        if (beg == end) continue;
        float2 a0 = make_float2(0.f, 0.f);
        float2 a1 = make_float2(0.f, 0.f);
        size_t rbase = (size_t)r * NN;
        int e = beg;
        for (; e + 2 <= end; e += 2) {
            uint32_t r0 = h[(rbase + g_srt[e])     * (FOUT / 2) + lane];
            uint32_t r1 = h[(rbase + g_srt[e + 1]) * (FOUT / 2) + lane];
            float2 f0 = __half22float2(*(__half2*)&r0);
            float2 f1 = __half22float2(*(__half2*)&r1);
            a0.x += f0.x; a0.y += f0.y;
            a1.x += f1.x; a1.y += f1.y;
        }
        if (e < end) {
            uint32_t r0 = h[(rbase + g_srt[e]) * (FOUT / 2) + lane];
            float2 f0 = __half22float2(*(__half2*)&r0);
            a0.x += f0.x; a0.y += f0.y;
        }
        float sc = g_dinv_in[idx];
        tot.x += sc * (a0.x + a1.x);
        tot.y += sc * (a0.y + a1.y);
    }
    ((float2*)out)[(size_t)w * (FOUT / 2) + lane] = tot;      // write-only (bias included)
}

// ---------------------------------------------------------------------------
// Launch — only genuine harness pointers cross host/device.
// ---------------------------------------------------------------------------
extern "C" void kernel_launch(void* const* d_in, const int* in_sizes, int n_in,
                              void* d_out, int out_size) {
    const float* x = nullptr; const int* esrc = nullptr; const int* edst = nullptr;
    const float* W1 = nullptr; const float* b1 = nullptr;
    const float* W2 = nullptr; const float* b2 = nullptr;
    for (int i = 0; i < n_in; i++) {
        switch (in_sizes[i]) {
            case NN * FIN:       x  = (const float*)d_in[i]; break;
            case RR * EE:        if (!esrc) esrc = (const int*)d_in[i];
                                 else       edst = (const int*)d_in[i]; break;
            case RR * FIN * FHID:  W1 = (const float*)d_in[i]; break;
            case RR * FHID:        b1 = (const float*)d_in[i]; break;
            case RR * FHID * FOUT: W2 = (const float*)d_in[i]; break;
            case RR * FOUT:        b2 = (const float*)d_in[i]; break;
            default: break;
        }
    }
    if (!x || !esrc || !edst || !W1 || !b1 || !W2 || !b2) {
        x    = (const float*)d_in[0];
        esrc = (const int*)  d_in[1];
        edst = (const int*)  d_in[2];
        W1   = (const float*)d_in[3];
        b1   = (const float*)d_in[4];
        W2   = (const float*)d_in[5];
        b2   = (const float*)d_in[6];
    }
    float* out = (float*)d_out;

    // 1) zero histogram + out-degree counters; pre-convert x / W1 to fp16
    zero_small<<<512, 256>>>();
    convert_x<<<2048, 256>>>(x);
    convert_w1<<<(RR * FIN * FHID + 255) / 256, 256>>>(W1);

    // 2) degrees -> rsqrt; bias sums
    degree_kernel<<<(RR * EE + 255) / 256, 256>>>(esrc, edst);
    rsqrt_kernel<<<(NSC + 255) / 256, 256>>>(b1, b2);

    // 3) CSR build
    scan1<<<NB, 256>>>();
    scan2<<<1, 512>>>();
    scan3<<<NB, 256>>>();
    place_kernel<<<(RR * EE + 255) / 256, 256>>>(esrc, edst);

    dim3 ggrid((NN + 127) / 128, 1, RR);
    int gather_grid = (NN * 32 + 255) / 256;

    // 4) layer 1: h1[r] = dinv_out (x16 @ W1_16[r]); acc1 = sum_r dinv_in * gather
    gemm1_f16<<<ggrid, 256>>>(NN);
    gather128_all<<<gather_grid, 256>>>();

    // 5) layer 2: h2[r] = dinv_out (relu(acc1+sb1) @ W2[r]); out = sb2 + sum_r gather
    gemm2_tc<FOUT><<<ggrid, 256>>>(W2, NN, FHID);
    gather64_all<<<gather_grid, 256>>>(out);
}